// round 11
// baseline (speedup 1.0000x reference)
#include <cuda_runtime.h>
#include <cuda_bf16.h>
#include <cstdint>

#define BB   4
#define SS   2048
#define DD   1024
#define HH   16
#define DK   64
#define MTOT (BB * SS)
#define D2   (DD / 2)   // u32 (bf16x2) per row

// bf16x2 hi/lo planes in global scratch (no runtime allocation allowed)
__device__ uint32_t g_xh[(size_t)MTOT * D2], g_xl[(size_t)MTOT * D2];
__device__ uint32_t g_qh[(size_t)MTOT * D2], g_ql[(size_t)MTOT * D2];
__device__ uint32_t g_kh[(size_t)MTOT * D2], g_kl[(size_t)MTOT * D2];
__device__ uint32_t g_vh[(size_t)MTOT * D2], g_vl[(size_t)MTOT * D2];
__device__ uint32_t g_ch[(size_t)MTOT * D2], g_cl[(size_t)MTOT * D2];
__device__ uint32_t g_wh[4][(size_t)DD * D2], g_wl[4][(size_t)DD * D2];

// ---------------------------------------------------------------------------
__device__ __forceinline__ void mma16(float* d,
                                      uint32_t a0, uint32_t a1, uint32_t a2, uint32_t a3,
                                      uint32_t b0, uint32_t b1) {
    asm volatile(
        "mma.sync.aligned.m16n8k16.row.col.f32.bf16.bf16.f32 "
        "{%0,%1,%2,%3},{%4,%5,%6,%7},{%8,%9},{%0,%1,%2,%3};"
        : "+f"(d[0]), "+f"(d[1]), "+f"(d[2]), "+f"(d[3])
        : "r"(a0), "r"(a1), "r"(a2), "r"(a3), "r"(b0), "r"(b1));
}

__device__ __forceinline__ void splitp(float x0, float x1, uint32_t& hi, uint32_t& lo) {
    __nv_bfloat162 h = __floats2bfloat162_rn(x0, x1);
    float f0 = __bfloat162float(h.x), f1 = __bfloat162float(h.y);
    __nv_bfloat162 l = __floats2bfloat162_rn(x0 - f0, x1 - f1);
    hi = *reinterpret_cast<uint32_t*>(&h);
    lo = *reinterpret_cast<uint32_t*>(&l);
}

__device__ __forceinline__ uint32_t smem_u32(const void* p) {
    uint32_t a;
    asm("{ .reg .u64 t; cvta.to.shared.u64 t, %1; cvt.u32.u64 %0, t; }"
        : "=r"(a) : "l"(p));
    return a;
}

__device__ __forceinline__ void ldmx4t(uint32_t& r0, uint32_t& r1,
                                       uint32_t& r2, uint32_t& r3, uint32_t addr) {
    asm volatile("ldmatrix.sync.aligned.m8n8.x4.trans.shared.b16 {%0,%1,%2,%3}, [%4];"
                 : "=r"(r0), "=r"(r1), "=r"(r2), "=r"(r3) : "r"(addr));
}

// ===========================================================================
// fp32 -> bf16 hi/lo plane conversion (one-shot, bandwidth-bound)
// ===========================================================================
__global__ __launch_bounds__(256) void convert_bf(
    const float* __restrict__ src, uint32_t* __restrict__ hi,
    uint32_t* __restrict__ lo, int n4)
{
    int i = blockIdx.x * blockDim.x + threadIdx.x;
    if (i >= n4) return;
    float4 v = ((const float4*)src)[i];
    uint32_t h0, l0, h1, l1;
    splitp(v.x, v.y, h0, l0);
    splitp(v.z, v.w, h1, l1);
    ((uint2*)hi)[i] = make_uint2(h0, h1);
    ((uint2*)lo)[i] = make_uint2(l0, l1);
}

// ===========================================================================
// GEMM on bf16 planes: C[8192,1024] = A[8192,1024] * W[1024,1024]^T
// 128x128 tile, BK=32, 256 threads (8 warps 4m x 2n), 3-term bf16.
// Epilogue: Cf != null -> fp32 out; else bf16 planes out (scaled).
// ===========================================================================
#define GSTR    20
#define G_AH    0
#define G_AL    2560
#define G_BH    5120
#define G_BL    7680
#define G_STAGE 10240
#define G_SMEM  (2 * G_STAGE * 4)   // 81920 B

__global__ __launch_bounds__(256, 2) void gemm_bf(
    const uint32_t* __restrict__ Ah, const uint32_t* __restrict__ Al,
    const uint32_t* __restrict__ Bh, const uint32_t* __restrict__ Bl,
    float* __restrict__ Cf, uint32_t* __restrict__ Ch, uint32_t* __restrict__ Cl,
    float scale)
{
    extern __shared__ uint32_t sm[];
    const int tid = threadIdx.x, lane = tid & 31, wid = tid >> 5;
    const int g = lane >> 2, t = lane & 3;
    const int wm = wid & 3, wn = wid >> 2;
    const int row0 = blockIdx.y * 128, col0 = blockIdx.x * 128;

    const uint32_t* Agh = Ah + (size_t)row0 * D2;
    const uint32_t* Agl = Al + (size_t)row0 * D2;
    const uint32_t* Bgh = Bh + (size_t)col0 * D2;
    const uint32_t* Bgl = Bl + (size_t)col0 * D2;

    // copy regs: per plane 512 uint4 chunks / 256 thr = 2 each
    uint4 rAh[2], rAl[2], rBh[2], rBl[2];
    float acc[2][8][4];
#pragma unroll
    for (int mb = 0; mb < 2; mb++)
#pragma unroll
        for (int nb = 0; nb < 8; nb++)
#pragma unroll
            for (int i = 0; i < 4; i++) acc[mb][nb][i] = 0.0f;

#define G_LD(kt) do {                                                          \
    _Pragma("unroll")                                                          \
    for (int i = 0; i < 2; i++) {                                              \
        int idx = tid + i * 256, r = idx >> 2, cu = (idx & 3) * 4;             \
        size_t go = (size_t)r * D2 + (kt) * 16 + cu;                           \
        rAh[i] = *(const uint4*)(Agh + go);                                    \
        rAl[i] = *(const uint4*)(Agl + go);                                    \
        rBh[i] = *(const uint4*)(Bgh + go);                                    \
        rBl[i] = *(const uint4*)(Bgl + go);                                    \
    } } while (0)

#define G_ST(s) do {                                                           \
    uint32_t* bs = sm + (s) * G_STAGE;                                         \
    _Pragma("unroll")                                                          \
    for (int i = 0; i < 2; i++) {                                              \
        int idx = tid + i * 256, r = idx >> 2, cu = (idx & 3) * 4;             \
        *(uint4*)(bs + G_AH + r * GSTR + cu) = rAh[i];                         \
        *(uint4*)(bs + G_AL + r * GSTR + cu) = rAl[i];                         \
        *(uint4*)(bs + G_BH + r * GSTR + cu) = rBh[i];                         \
        *(uint4*)(bs + G_BL + r * GSTR + cu) = rBl[i];                         \
    } } while (0)

    G_LD(0); G_ST(0); G_LD(1);

    for (int kt = 0; kt < 32; kt++) {
        const int s = kt & 1;
        __syncthreads();
        if (kt + 1 < 32) G_ST((kt + 1) & 1);
        if (kt + 2 < 32) G_LD(kt + 2);

        const uint32_t* st = sm + s * G_STAGE;
#pragma unroll
        for (int ks = 0; ks < 2; ks++) {
            const int ko = ks * 8;
            uint32_t ah[2][4], al[2][4];
#pragma unroll
            for (int mb = 0; mb < 2; mb++) {
                int ab = (wm * 32 + mb * 16 + g) * GSTR + ko + t;
                ah[mb][0] = st[G_AH + ab];            ah[mb][1] = st[G_AH + ab + 8 * GSTR];
                ah[mb][2] = st[G_AH + ab + 4];        ah[mb][3] = st[G_AH + ab + 8 * GSTR + 4];
                al[mb][0] = st[G_AL + ab];            al[mb][1] = st[G_AL + ab + 8 * GSTR];
                al[mb][2] = st[G_AL + ab + 4];        al[mb][3] = st[G_AL + ab + 8 * GSTR + 4];
            }
#pragma unroll
            for (int nb = 0; nb < 8; nb++) {
                int bb = (wn * 64 + nb * 8 + g) * GSTR + ko + t;
                uint32_t bh0 = st[G_BH + bb], bh1 = st[G_BH + bb + 4];
                uint32_t bl0 = st[G_BL + bb], bl1 = st[G_BL + bb + 4];
#pragma unroll
                for (int mb = 0; mb < 2; mb++) {
                    mma16(acc[mb][nb], ah[mb][0], ah[mb][1], ah[mb][2], ah[mb][3], bh0, bh1);
                    mma16(acc[mb][nb], ah[mb][0], ah[mb][1], ah[mb][2], ah[mb][3], bl0, bl1);
                    mma16(acc[mb][nb], al[mb][0], al[mb][1], al[mb][2], al[mb][3], bh0, bh1);
                }
            }
        }
    }

    if (Cf) {
#pragma unroll
        for (int mb = 0; mb < 2; mb++) {
            int r = row0 + wm * 32 + mb * 16 + g;
#pragma unroll
            for (int nb = 0; nb < 8; nb++) {
                int c = col0 + wn * 64 + nb * 8 + 2 * t;
                *(float2*)(Cf + (size_t)r * DD + c)       = make_float2(acc[mb][nb][0], acc[mb][nb][1]);
                *(float2*)(Cf + (size_t)(r + 8) * DD + c) = make_float2(acc[mb][nb][2], acc[mb][nb][3]);
            }
        }
    } else {
#pragma unroll
        for (int mb = 0; mb < 2; mb++) {
            int r = row0 + wm * 32 + mb * 16 + g;
#pragma unroll
            for (int nb = 0; nb < 8; nb++) {
                int c2 = col0 / 2 + wn * 32 + nb * 4 + t;
                uint32_t hw, lw;
                splitp(acc[mb][nb][0] * scale, acc[mb][nb][1] * scale, hw, lw);
                Ch[(size_t)r * D2 + c2] = hw; Cl[(size_t)r * D2 + c2] = lw;
                splitp(acc[mb][nb][2] * scale, acc[mb][nb][3] * scale, hw, lw);
                Ch[(size_t)(r + 8) * D2 + c2] = hw; Cl[(size_t)(r + 8) * D2 + c2] = lw;
            }
        }
    }
}

// ===========================================================================
// Flash attention v3 on bf16 planes: 128q x 32k tiles, 256 threads.
// Pure-copy smem fills; P in registers; V via ldmatrix.x4.trans.
// Writes ctx as bf16 planes for the O-projection GEMM.
// ===========================================================================
#define AQH 0
#define AQL 4608
#define AKH 9216
#define AKL 10368
#define AVH 11520
#define AVL 12672
#define A_SMEM (13824 * 4)   // 55296 B
#define QSTR 36
#define KSTR 36
#define VSTR 36

__global__ __launch_bounds__(256, 2) void attn_tc(
    const uint32_t* __restrict__ qh, const uint32_t* __restrict__ ql,
    const uint32_t* __restrict__ kh, const uint32_t* __restrict__ kl,
    const uint32_t* __restrict__ vh, const uint32_t* __restrict__ vl,
    uint32_t* __restrict__ ch, uint32_t* __restrict__ cl)
{
    extern __shared__ uint32_t sm[];
    const uint32_t sb = smem_u32(sm);
    const int tid = threadIdx.x, lane = tid & 31, wid = tid >> 5;
    const int g = lane >> 2, t = lane & 3;
    const int b = blockIdx.z, h = blockIdx.y, q0 = blockIdx.x * 128;

    const size_t qrow0 = (size_t)(b * SS) + q0;
    const size_t krow0 = (size_t)(b * SS);
    const int hcol = h * (DK / 2);   // u32 column offset of this head

    // Q planes: 128 rows x 32 u32 per plane -> 4 uint4 per plane per thread
#pragma unroll
    for (int i = 0; i < 4; i++) {
        int idx = tid + i * 256, r = idx >> 3, cu = (idx & 7) * 4;
        size_t go = (qrow0 + r) * D2 + hcol + cu;
        *(uint4*)(sm + AQH + r * QSTR + cu) = *(const uint4*)(qh + go);
        *(uint4*)(sm + AQL + r * QSTR + cu) = *(const uint4*)(ql + go);
    }

    const int lrow = lane & 7, q4 = lane >> 3;
    const int lm_row = (q4 & 1) * 8 + lrow;
    const int lm_dk  = (q4 >> 1) * 8;

    float m0 = -1e30f, m1 = -1e30f, l0s = 0.0f, l1s = 0.0f;
    float oacc[8][4];
#pragma unroll
    for (int nb = 0; nb < 8; nb++)
#pragma unroll
        for (int i = 0; i < 4; i++) oacc[nb][i] = 0.0f;

    for (int kt = 0; kt < SS / 32; kt++) {
        __syncthreads();   // previous tile's consumers done
        // K/V planes: 32 rows x 32 u32 each -> 1 uint4 per plane per thread
        {
            int r = tid >> 3, cu = (tid & 7) * 4;
            size_t go = (krow0 + kt * 32 + r) * D2 + hcol + cu;
            *(uint4*)(sm + AKH + r * KSTR + cu) = *(const uint4*)(kh + go);
            *(uint4*)(sm + AKL + r * KSTR + cu) = *(const uint4*)(kl + go);
            *(uint4*)(sm + AVH + r * VSTR + cu) = *(const uint4*)(vh + go);
            *(uint4*)(sm + AVL + r * VSTR + cu) = *(const uint4*)(vl + go);
        }
        __syncthreads();

        // S[16 x 32] = Q * K^T per warp
        float sacc[4][4];
#pragma unroll
        for (int nb = 0; nb < 4; nb++)
#pragma unroll
            for (int i = 0; i < 4; i++) sacc[nb][i] = 0.0f;
#pragma unroll
        for (int ks = 0; ks < 4; ks++) {
            const int ko = ks * 8;
            int ab = (wid * 16 + g) * QSTR + ko + t;
            uint32_t ah0 = sm[AQH + ab],     ah1 = sm[AQH + ab + 8 * QSTR];
            uint32_t ah2 = sm[AQH + ab + 4], ah3 = sm[AQH + ab + 8 * QSTR + 4];
            uint32_t al0 = sm[AQL + ab],     al1 = sm[AQL + ab + 8 * QSTR];
            uint32_t al2 = sm[AQL + ab + 4], al3 = sm[AQL + ab + 8 * QSTR + 4];
#pragma unroll
            for (int nb = 0; nb < 4; nb++) {
                int bb = (nb * 8 + g) * KSTR + ko + t;
                uint32_t bh0 = sm[AKH + bb], bh1 = sm[AKH + bb + 4];
                uint32_t bl0 = sm[AKL + bb], bl1 = sm[AKL + bb + 4];
                mma16(sacc[nb], ah0, ah1, ah2, ah3, bh0, bh1);
                mma16(sacc[nb], ah0, ah1, ah2, ah3, bl0, bl1);
                mma16(sacc[nb], al0, al1, al2, al3, bh0, bh1);
            }
        }

        // online softmax (warp-private)
        float rm0 = -1e30f, rm1 = -1e30f;
#pragma unroll
        for (int nb = 0; nb < 4; nb++) {
            rm0 = fmaxf(rm0, fmaxf(sacc[nb][0], sacc[nb][1]));
            rm1 = fmaxf(rm1, fmaxf(sacc[nb][2], sacc[nb][3]));
        }
        rm0 = fmaxf(rm0, __shfl_xor_sync(0xffffffffu, rm0, 1));
        rm0 = fmaxf(rm0, __shfl_xor_sync(0xffffffffu, rm0, 2));
        rm1 = fmaxf(rm1, __shfl_xor_sync(0xffffffffu, rm1, 1));
        rm1 = fmaxf(rm1, __shfl_xor_sync(0xffffffffu, rm1, 2));
        float mn0 = fmaxf(m0, rm0), mn1 = fmaxf(m1, rm1);
        float a0 = __expf(m0 - mn0), a1 = __expf(m1 - mn1);
        m0 = mn0; m1 = mn1;

        float ls0 = 0.0f, ls1 = 0.0f;
        uint32_t pfh[2][4], pfl[2][4];
#pragma unroll
        for (int nb = 0; nb < 4; nb++) {
            float p0 = __expf(sacc[nb][0] - mn0), p1 = __expf(sacc[nb][1] - mn0);
            float p2 = __expf(sacc[nb][2] - mn1), p3 = __expf(sacc[nb][3] - mn1);
            ls0 += p0 + p1; ls1 += p2 + p3;
            const int ks = nb >> 1, half = nb & 1;
            splitp(p0, p1, pfh[ks][2 * half],     pfl[ks][2 * half]);
            splitp(p2, p3, pfh[ks][2 * half + 1], pfl[ks][2 * half + 1]);
        }
        ls0 += __shfl_xor_sync(0xffffffffu, ls0, 1);
        ls0 += __shfl_xor_sync(0xffffffffu, ls0, 2);
        ls1 += __shfl_xor_sync(0xffffffffu, ls1, 1);
        ls1 += __shfl_xor_sync(0xffffffffu, ls1, 2);
        l0s = l0s * a0 + ls0; l1s = l1s * a1 + ls1;
#pragma unroll
        for (int nb = 0; nb < 8; nb++) {
            oacc[nb][0] *= a0; oacc[nb][1] *= a0;
            oacc[nb][2] *= a1; oacc[nb][3] *= a1;
        }

        // O += P * V (V B-frags via ldmatrix.x4.trans)
#pragma unroll
        for (int ks = 0; ks < 2; ks++) {
#pragma unroll
            for (int nbp = 0; nbp < 4; nbp++) {
                const int dk0 = nbp * 16;
                uint32_t off = (uint32_t)((ks * 16 + lm_row) * VSTR + (dk0 + lm_dk) / 2);
                uint32_t vh0, vh1, vh2, vh3, vl0, vl1, vl2, vl3;
                ldmx4t(vh0, vh1, vh2, vh3, sb + 4 * (AVH + off));
                ldmx4t(vl0, vl1, vl2, vl3, sb + 4 * (AVL + off));
                float* d0 = oacc[2 * nbp];
                float* d1 = oacc[2 * nbp + 1];
                mma16(d0, pfh[ks][0], pfh[ks][1], pfh[ks][2], pfh[ks][3], vh0, vh1);
                mma16(d0, pfh[ks][0], pfh[ks][1], pfh[ks][2], pfh[ks][3], vl0, vl1);
                mma16(d0, pfl[ks][0], pfl[ks][1], pfl[ks][2], pfl[ks][3], vh0, vh1);
                mma16(d1, pfh[ks][0], pfh[ks][1], pfh[ks][2], pfh[ks][3], vh2, vh3);
                mma16(d1, pfh[ks][0], pfh[ks][1], pfh[ks][2], pfh[ks][3], vl2, vl3);
                mma16(d1, pfl[ks][0], pfl[ks][1], pfl[ks][2], pfl[ks][3], vh2, vh3);
            }
        }
    }

    // epilogue: write ctx as bf16 planes
    const float inv0 = 1.0f / l0s, inv1 = 1.0f / l1s;
#pragma unroll
    for (int nb = 0; nb < 8; nb++) {
        size_t r = qrow0 + wid * 16 + g;
        int c2 = hcol + nb * 4 + t;
        uint32_t hw, lw;
        splitp(oacc[nb][0] * inv0, oacc[nb][1] * inv0, hw, lw);
        ch[r * D2 + c2] = hw; cl[r * D2 + c2] = lw;
        splitp(oacc[nb][2] * inv1, oacc[nb][3] * inv1, hw, lw);
        ch[(r + 8) * D2 + c2] = hw; cl[(r + 8) * D2 + c2] = lw;
    }
}

// ---------------------------------------------------------------------------
extern "C" void kernel_launch(void* const* d_in, const int* in_sizes, int n_in,
                              void* d_out, int out_size)
{
    const float* x = (const float*)d_in[0];
    const float* W[4] = {(const float*)d_in[1], (const float*)d_in[2],
                         (const float*)d_in[3], (const float*)d_in[4]};

    uint32_t *xh, *xl, *qh, *ql, *kh, *kl, *vh, *vl, *ch, *cl, *wh, *wl;
    cudaGetSymbolAddress((void**)&xh, g_xh); cudaGetSymbolAddress((void**)&xl, g_xl);
    cudaGetSymbolAddress((void**)&qh, g_qh); cudaGetSymbolAddress((void**)&ql, g_ql);
    cudaGetSymbolAddress((void**)&kh, g_kh); cudaGetSymbolAddress((void**)&kl, g_kl);
    cudaGetSymbolAddress((void**)&vh, g_vh); cudaGetSymbolAddress((void**)&vl, g_vl);
    cudaGetSymbolAddress((void**)&ch, g_ch); cudaGetSymbolAddress((void**)&cl, g_cl);
    cudaGetSymbolAddress((void**)&wh, g_wh); cudaGetSymbolAddress((void**)&wl, g_wl);

    cudaFuncSetAttribute(gemm_bf, cudaFuncAttributeMaxDynamicSharedMemorySize, G_SMEM);
    cudaFuncSetAttribute(attn_tc, cudaFuncAttributeMaxDynamicSharedMemorySize, A_SMEM);

    // 1) convert inputs to bf16 hi/lo planes
    const int xn4 = MTOT * DD / 4, wn4 = DD * DD / 4;
    convert_bf<<<(xn4 + 255) / 256, 256>>>(x, xh, xl, xn4);
    for (int w = 0; w < 4; w++)
        convert_bf<<<(wn4 + 255) / 256, 256>>>(W[w], wh + (size_t)w * DD * D2,
                                               wl + (size_t)w * DD * D2, wn4);

    // 2) projections (Q scaled by 1/sqrt(DK) = 0.125 in epilogue)
    dim3 gg(DD / 128, MTOT / 128);   // (8, 64)
    gemm_bf<<<gg, 256, G_SMEM>>>(xh, xl, wh + 0 * (size_t)DD * D2, wl + 0 * (size_t)DD * D2,
                                 nullptr, qh, ql, 0.125f);
    gemm_bf<<<gg, 256, G_SMEM>>>(xh, xl, wh + 1 * (size_t)DD * D2, wl + 1 * (size_t)DD * D2,
                                 nullptr, kh, kl, 1.0f);
    gemm_bf<<<gg, 256, G_SMEM>>>(xh, xl, wh + 2 * (size_t)DD * D2, wl + 2 * (size_t)DD * D2,
                                 nullptr, vh, vl, 1.0f);

    // 3) attention (writes ctx planes)
    attn_tc<<<dim3(SS / 128, HH, BB), 256, A_SMEM>>>(qh, ql, kh, kl, vh, vl, ch, cl);

    // 4) output projection -> fp32 d_out
    gemm_bf<<<gg, 256, G_SMEM>>>(ch, cl, wh + 3 * (size_t)DD * D2, wl + 3 * (size_t)DD * D2,
                                 (float*)d_out, nullptr, nullptr, 1.0f);
}

// round 13
// speedup vs baseline: 1.1430x; 1.1430x over previous
#include <cuda_runtime.h>
#include <cuda_bf16.h>
#include <cstdint>

#define BB   4
#define SS   2048
#define DD   1024
#define HH   16
#define DK   64
#define MTOT (BB * SS)
#define D2   (DD / 2)   // u32 (bf16x2) per row

// bf16x2 hi/lo planes in global scratch (no runtime allocation allowed)
__device__ uint32_t g_xh[(size_t)MTOT * D2], g_xl[(size_t)MTOT * D2];
__device__ uint32_t g_qh[(size_t)MTOT * D2], g_ql[(size_t)MTOT * D2];
__device__ uint32_t g_kh[(size_t)MTOT * D2], g_kl[(size_t)MTOT * D2];
__device__ uint32_t g_vh[(size_t)MTOT * D2], g_vl[(size_t)MTOT * D2];
__device__ uint32_t g_ch[(size_t)MTOT * D2], g_cl[(size_t)MTOT * D2];
__device__ uint32_t g_wh[4][(size_t)DD * D2], g_wl[4][(size_t)DD * D2];

// ---------------------------------------------------------------------------
__device__ __forceinline__ void mma16(float* d,
                                      uint32_t a0, uint32_t a1, uint32_t a2, uint32_t a3,
                                      uint32_t b0, uint32_t b1) {
    asm volatile(
        "mma.sync.aligned.m16n8k16.row.col.f32.bf16.bf16.f32 "
        "{%0,%1,%2,%3},{%4,%5,%6,%7},{%8,%9},{%0,%1,%2,%3};"
        : "+f"(d[0]), "+f"(d[1]), "+f"(d[2]), "+f"(d[3])
        : "r"(a0), "r"(a1), "r"(a2), "r"(a3), "r"(b0), "r"(b1));
}

__device__ __forceinline__ void splitp(float x0, float x1, uint32_t& hi, uint32_t& lo) {
    __nv_bfloat162 h = __floats2bfloat162_rn(x0, x1);
    float f0 = __bfloat162float(h.x), f1 = __bfloat162float(h.y);
    __nv_bfloat162 l = __floats2bfloat162_rn(x0 - f0, x1 - f1);
    hi = *reinterpret_cast<uint32_t*>(&h);
    lo = *reinterpret_cast<uint32_t*>(&l);
}

__device__ __forceinline__ uint32_t smem_u32(const void* p) {
    uint32_t a;
    asm("{ .reg .u64 t; cvta.to.shared.u64 t, %1; cvt.u32.u64 %0, t; }"
        : "=r"(a) : "l"(p));
    return a;
}

__device__ __forceinline__ void ldmx4(uint32_t& r0, uint32_t& r1,
                                      uint32_t& r2, uint32_t& r3, uint32_t addr) {
    asm volatile("ldmatrix.sync.aligned.m8n8.x4.shared.b16 {%0,%1,%2,%3}, [%4];"
                 : "=r"(r0), "=r"(r1), "=r"(r2), "=r"(r3) : "r"(addr));
}

__device__ __forceinline__ void ldmx4t(uint32_t& r0, uint32_t& r1,
                                       uint32_t& r2, uint32_t& r3, uint32_t addr) {
    asm volatile("ldmatrix.sync.aligned.m8n8.x4.trans.shared.b16 {%0,%1,%2,%3}, [%4];"
                 : "=r"(r0), "=r"(r1), "=r"(r2), "=r"(r3) : "r"(addr));
}

#define CP16(dst_u32, src) \
    asm volatile("cp.async.cg.shared.global [%0], [%1], 16;" \
                 :: "r"(sb + 4u * (uint32_t)(dst_u32)), "l"((const void*)(src)))
#define CP_COMMIT() asm volatile("cp.async.commit_group;")
#define CP_WAIT(n)  asm volatile("cp.async.wait_group %0;" :: "n"(n))

// ===========================================================================
// fp32 -> bf16 hi/lo plane conversion (one-shot, bandwidth-bound)
// ===========================================================================
__global__ __launch_bounds__(256) void convert_bf(
    const float* __restrict__ src, uint32_t* __restrict__ hi,
    uint32_t* __restrict__ lo, int n4)
{
    int i = blockIdx.x * blockDim.x + threadIdx.x;
    if (i >= n4) return;
    float4 v = ((const float4*)src)[i];
    uint32_t h0, l0, h1, l1;
    splitp(v.x, v.y, h0, l0);
    splitp(v.z, v.w, h1, l1);
    ((uint2*)hi)[i] = make_uint2(h0, h1);
    ((uint2*)lo)[i] = make_uint2(l0, l1);
}

// ===========================================================================
// GEMM on bf16 planes, cp.async pipeline + ldmatrix fragments.
// C[8192,1024] = A[8192,1024] * W[1024,1024]^T ; 128x128 tile, BK=32.
// ===========================================================================
#define GSTR    20
#define G_AH    0
#define G_AL    2560
#define G_BH    5120
#define G_BL    7680
#define G_STAGE 10240
#define G_SMEM  (2 * G_STAGE * 4)   // 81920 B

__global__ __launch_bounds__(256, 2) void gemm_bf(
    const uint32_t* __restrict__ Ah, const uint32_t* __restrict__ Al,
    const uint32_t* __restrict__ Bh, const uint32_t* __restrict__ Bl,
    float* __restrict__ Cf, uint32_t* __restrict__ Ch, uint32_t* __restrict__ Cl,
    float scale)
{
    extern __shared__ uint32_t sm[];
    const uint32_t sb = smem_u32(sm);
    const int tid = threadIdx.x, lane = tid & 31, wid = tid >> 5;
    const int g = lane >> 2, t = lane & 3;
    const int wm = wid & 3, wn = wid >> 2;
    const int row0 = blockIdx.y * 128, col0 = blockIdx.x * 128;

    const uint32_t* Agh = Ah + (size_t)row0 * D2;
    const uint32_t* Agl = Al + (size_t)row0 * D2;
    const uint32_t* Bgh = Bh + (size_t)col0 * D2;
    const uint32_t* Bgl = Bl + (size_t)col0 * D2;

    // ldmatrix lane addressing
    const int a_lr = lane & 15, a_lk = (lane >> 4) * 4;
    const int b_lc = (lane & 7) + ((lane >> 4) << 3), b_lk = ((lane >> 3) & 1) * 4;

    float acc[2][8][4];
#pragma unroll
    for (int mb = 0; mb < 2; mb++)
#pragma unroll
        for (int nb = 0; nb < 8; nb++)
#pragma unroll
            for (int i = 0; i < 4; i++) acc[mb][nb][i] = 0.0f;

#define G_ISSUE(kt) do {                                                       \
    uint32_t bs_ = ((kt) & 1) * G_STAGE;                                       \
    _Pragma("unroll")                                                          \
    for (int i = 0; i < 2; i++) {                                              \
        int idx = tid + i * 256, r = idx >> 2, cu = (idx & 3) * 4;             \
        size_t go = (size_t)r * D2 + (kt) * 16 + cu;                           \
        uint32_t so = r * GSTR + cu;                                           \
        CP16(bs_ + G_AH + so, Agh + go);                                       \
        CP16(bs_ + G_AL + so, Agl + go);                                       \
        CP16(bs_ + G_BH + so, Bgh + go);                                       \
        CP16(bs_ + G_BL + so, Bgl + go);                                       \
    } } while (0)

    G_ISSUE(0); CP_COMMIT();
    G_ISSUE(1); CP_COMMIT();

    for (int kt = 0; kt < 32; kt++) {
        if (kt == 31) { CP_WAIT(0); } else { CP_WAIT(1); }
        __syncthreads();

        const uint32_t bs = (kt & 1) * G_STAGE;
#pragma unroll
        for (int ks = 0; ks < 2; ks++) {
            const int ko = ks * 8;
            uint32_t ah[2][4], al[2][4];
#pragma unroll
            for (int mb = 0; mb < 2; mb++) {
                uint32_t ao = bs + G_AH + (wm * 32 + mb * 16 + a_lr) * GSTR + ko + a_lk;
                ldmx4(ah[mb][0], ah[mb][1], ah[mb][2], ah[mb][3], sb + 4 * ao);
                ldmx4(al[mb][0], al[mb][1], al[mb][2], al[mb][3], sb + 4 * (ao + 2560));
            }
#pragma unroll
            for (int nbp = 0; nbp < 4; nbp++) {
                uint32_t bo = bs + G_BH + (wn * 64 + nbp * 16 + b_lc) * GSTR + ko + b_lk;
                uint32_t bh0, bh1, bh2, bh3, bl0, bl1, bl2, bl3;
                ldmx4(bh0, bh1, bh2, bh3, sb + 4 * bo);
                ldmx4(bl0, bl1, bl2, bl3, sb + 4 * (bo + 2560));
#pragma unroll
                for (int mb = 0; mb < 2; mb++) {
                    float* d0 = acc[mb][2 * nbp];
                    float* d1 = acc[mb][2 * nbp + 1];
                    mma16(d0, ah[mb][0], ah[mb][1], ah[mb][2], ah[mb][3], bh0, bh1);
                    mma16(d0, ah[mb][0], ah[mb][1], ah[mb][2], ah[mb][3], bl0, bl1);
                    mma16(d0, al[mb][0], al[mb][1], al[mb][2], al[mb][3], bh0, bh1);
                    mma16(d1, ah[mb][0], ah[mb][1], ah[mb][2], ah[mb][3], bh2, bh3);
                    mma16(d1, ah[mb][0], ah[mb][1], ah[mb][2], ah[mb][3], bl2, bl3);
                    mma16(d1, al[mb][0], al[mb][1], al[mb][2], al[mb][3], bh2, bh3);
                }
            }
        }
        __syncthreads();
        if (kt + 2 < 32) { G_ISSUE(kt + 2); CP_COMMIT(); }
    }

    if (Cf) {
#pragma unroll
        for (int mb = 0; mb < 2; mb++) {
            int r = row0 + wm * 32 + mb * 16 + g;
#pragma unroll
            for (int nb = 0; nb < 8; nb++) {
                int c = col0 + wn * 64 + nb * 8 + 2 * t;
                *(float2*)(Cf + (size_t)r * DD + c)       = make_float2(acc[mb][nb][0], acc[mb][nb][1]);
                *(float2*)(Cf + (size_t)(r + 8) * DD + c) = make_float2(acc[mb][nb][2], acc[mb][nb][3]);
            }
        }
    } else {
#pragma unroll
        for (int mb = 0; mb < 2; mb++) {
            int r = row0 + wm * 32 + mb * 16 + g;
#pragma unroll
            for (int nb = 0; nb < 8; nb++) {
                int c2 = col0 / 2 + wn * 32 + nb * 4 + t;
                uint32_t hw, lw;
                splitp(acc[mb][nb][0] * scale, acc[mb][nb][1] * scale, hw, lw);
                Ch[(size_t)r * D2 + c2] = hw; Cl[(size_t)r * D2 + c2] = lw;
                splitp(acc[mb][nb][2] * scale, acc[mb][nb][3] * scale, hw, lw);
                Ch[(size_t)(r + 8) * D2 + c2] = hw; Cl[(size_t)(r + 8) * D2 + c2] = lw;
            }
        }
    }
}

// ===========================================================================
// Flash attention: 128q x 32k tiles, 256 threads, cp.async K/V double buffer.
// P in registers; V B-frags via ldmatrix.x4.trans. bf16 planes in and out.
// smem: QH 0, QL 4608; stage s at 9216+s*4608: KH+0, KL+1152, VH+2304, VL+3456
// ===========================================================================
#define AQH  0
#define AQL  4608
#define AST  9216
#define ASTG 4608
#define A_SMEM (18432 * 4)   // 73728 B
#define QSTR 36
#define KSTR 36
#define VSTR 36

__global__ __launch_bounds__(256, 2) void attn_tc(
    const uint32_t* __restrict__ qh, const uint32_t* __restrict__ ql,
    const uint32_t* __restrict__ kh, const uint32_t* __restrict__ kl,
    const uint32_t* __restrict__ vh, const uint32_t* __restrict__ vl,
    uint32_t* __restrict__ ch, uint32_t* __restrict__ cl)
{
    extern __shared__ uint32_t sm[];
    const uint32_t sb = smem_u32(sm);
    const int tid = threadIdx.x, lane = tid & 31, wid = tid >> 5;
    const int g = lane >> 2, t = lane & 3;
    const int b = blockIdx.z, h = blockIdx.y, q0 = blockIdx.x * 128;

    const size_t qrow0 = (size_t)(b * SS) + q0;
    const size_t krow0 = (size_t)(b * SS);
    const int hcol = h * (DK / 2);

    // Q planes: plain vector loads (one-shot)
#pragma unroll
    for (int i = 0; i < 4; i++) {
        int idx = tid + i * 256, r = idx >> 3, cu = (idx & 7) * 4;
        size_t go = (qrow0 + r) * D2 + hcol + cu;
        *(uint4*)(sm + AQH + r * QSTR + cu) = *(const uint4*)(qh + go);
        *(uint4*)(sm + AQL + r * QSTR + cu) = *(const uint4*)(ql + go);
    }

    // cp.async K/V issue: 4 planes x 32 rows x 32 u32 = 1024 uint4 per stage
    // -> 4 chunks per thread (i < 4; pl = idx>>8)
#define A_ISSUE(kt) do {                                                       \
    uint32_t stg_ = AST + ((kt) & 1) * ASTG;                                   \
    _Pragma("unroll")                                                          \
    for (int i = 0; i < 4; i++) {                                              \
        int idx = tid + i * 256;                                               \
        int pl = idx >> 8, j = idx & 255, r = j >> 3, cu = (j & 7) * 4;        \
        const uint32_t* sp = (pl == 0) ? kh : (pl == 1) ? kl                   \
                             : (pl == 2) ? vh : vl;                            \
        size_t go = (krow0 + (kt) * 32 + r) * D2 + hcol + cu;                  \
        CP16(stg_ + pl * 1152 + r * 36 + cu, sp + go);                         \
    } } while (0)

    const int lrow = lane & 7, q4 = lane >> 3;
    const int lm_row = (q4 & 1) * 8 + lrow;
    const int lm_dk  = (q4 >> 1) * 8;

    float m0 = -1e30f, m1 = -1e30f, l0s = 0.0f, l1s = 0.0f;
    float oacc[8][4];
#pragma unroll
    for (int nb = 0; nb < 8; nb++)
#pragma unroll
        for (int i = 0; i < 4; i++) oacc[nb][i] = 0.0f;

    A_ISSUE(0); CP_COMMIT();

    for (int kt = 0; kt < SS / 32; kt++) {
        if (kt + 1 < SS / 32) {
            A_ISSUE(kt + 1); CP_COMMIT();
            CP_WAIT(1);
        } else {
            CP_WAIT(0);
        }
        __syncthreads();

        const uint32_t stg = AST + (kt & 1) * ASTG;
        const uint32_t AKH_ = stg, AKL_ = stg + 1152;
        const uint32_t AVH_ = stg + 2304, AVL_ = stg + 3456;

        // S[16 x 32] = Q * K^T per warp
        float sacc[4][4];
#pragma unroll
        for (int nb = 0; nb < 4; nb++)
#pragma unroll
            for (int i = 0; i < 4; i++) sacc[nb][i] = 0.0f;
#pragma unroll
        for (int ks = 0; ks < 4; ks++) {
            const int ko = ks * 8;
            int ab = (wid * 16 + g) * QSTR + ko + t;
            uint32_t ah0 = sm[AQH + ab],     ah1 = sm[AQH + ab + 8 * QSTR];
            uint32_t ah2 = sm[AQH + ab + 4], ah3 = sm[AQH + ab + 8 * QSTR + 4];
            uint32_t al0 = sm[AQL + ab],     al1 = sm[AQL + ab + 8 * QSTR];
            uint32_t al2 = sm[AQL + ab + 4], al3 = sm[AQL + ab + 8 * QSTR + 4];
#pragma unroll
            for (int nb = 0; nb < 4; nb++) {
                int bb = (nb * 8 + g) * KSTR + ko + t;
                uint32_t bh0 = sm[AKH_ + bb], bh1 = sm[AKH_ + bb + 4];
                uint32_t bl0 = sm[AKL_ + bb], bl1 = sm[AKL_ + bb + 4];
                mma16(sacc[nb], ah0, ah1, ah2, ah3, bh0, bh1);
                mma16(sacc[nb], ah0, ah1, ah2, ah3, bl0, bl1);
                mma16(sacc[nb], al0, al1, al2, al3, bh0, bh1);
            }
        }

        // online softmax (warp-private)
        float rm0 = -1e30f, rm1 = -1e30f;
#pragma unroll
        for (int nb = 0; nb < 4; nb++) {
            rm0 = fmaxf(rm0, fmaxf(sacc[nb][0], sacc[nb][1]));
            rm1 = fmaxf(rm1, fmaxf(sacc[nb][2], sacc[nb][3]));
        }
        rm0 = fmaxf(rm0, __shfl_xor_sync(0xffffffffu, rm0, 1));
        rm0 = fmaxf(rm0, __shfl_xor_sync(0xffffffffu, rm0, 2));
        rm1 = fmaxf(rm1, __shfl_xor_sync(0xffffffffu, rm1, 1));
        rm1 = fmaxf(rm1, __shfl_xor_sync(0xffffffffu, rm1, 2));
        float mn0 = fmaxf(m0, rm0), mn1 = fmaxf(m1, rm1);
        float a0 = __expf(m0 - mn0), a1 = __expf(m1 - mn1);
        m0 = mn0; m1 = mn1;

        float ls0 = 0.0f, ls1 = 0.0f;
        uint32_t pfh[2][4], pfl[2][4];
#pragma unroll
        for (int nb = 0; nb < 4; nb++) {
            float p0 = __expf(sacc[nb][0] - mn0), p1 = __expf(sacc[nb][1] - mn0);
            float p2 = __expf(sacc[nb][2] - mn1), p3 = __expf(sacc[nb][3] - mn1);
            ls0 += p0 + p1; ls1 += p2 + p3;
            const int ks = nb >> 1, half = nb & 1;
            splitp(p0, p1, pfh[ks][2 * half],     pfl[ks][2 * half]);
            splitp(p2, p3, pfh[ks][2 * half + 1], pfl[ks][2 * half + 1]);
        }
        ls0 += __shfl_xor_sync(0xffffffffu, ls0, 1);
        ls0 += __shfl_xor_sync(0xffffffffu, ls0, 2);
        ls1 += __shfl_xor_sync(0xffffffffu, ls1, 1);
        ls1 += __shfl_xor_sync(0xffffffffu, ls1, 2);
        l0s = l0s * a0 + ls0; l1s = l1s * a1 + ls1;
#pragma unroll
        for (int nb = 0; nb < 8; nb++) {
            oacc[nb][0] *= a0; oacc[nb][1] *= a0;
            oacc[nb][2] *= a1; oacc[nb][3] *= a1;
        }

        // O += P * V (V B-frags via ldmatrix.x4.trans)
#pragma unroll
        for (int ks = 0; ks < 2; ks++) {
#pragma unroll
            for (int nbp = 0; nbp < 4; nbp++) {
                const int dk0 = nbp * 16;
                uint32_t off = (uint32_t)((ks * 16 + lm_row) * VSTR + (dk0 + lm_dk) / 2);
                uint32_t vh0, vh1, vh2, vh3, vl0, vl1, vl2, vl3;
                ldmx4t(vh0, vh1, vh2, vh3, sb + 4 * (AVH_ + off));
                ldmx4t(vl0, vl1, vl2, vl3, sb + 4 * (AVL_ + off));
                float* d0 = oacc[2 * nbp];
                float* d1 = oacc[2 * nbp + 1];
                mma16(d0, pfh[ks][0], pfh[ks][1], pfh[ks][2], pfh[ks][3], vh0, vh1);
                mma16(d0, pfh[ks][0], pfh[ks][1], pfh[ks][2], pfh[ks][3], vl0, vl1);
                mma16(d0, pfl[ks][0], pfl[ks][1], pfl[ks][2], pfl[ks][3], vh0, vh1);
                mma16(d1, pfh[ks][0], pfh[ks][1], pfh[ks][2], pfh[ks][3], vh2, vh3);
                mma16(d1, pfh[ks][0], pfh[ks][1], pfh[ks][2], pfh[ks][3], vl2, vl3);
                mma16(d1, pfl[ks][0], pfl[ks][1], pfl[ks][2], pfl[ks][3], vh2, vh3);
            }
        }
        __syncthreads();
    }

    // epilogue: write ctx as bf16 planes
    const float inv0 = 1.0f / l0s, inv1 = 1.0f / l1s;
#pragma unroll
    for (int nb = 0; nb < 8; nb++) {
        size_t r = qrow0 + wid * 16 + g;
        int c2 = hcol + nb * 4 + t;
        uint32_t hw, lw;
        splitp(oacc[nb][0] * inv0, oacc[nb][1] * inv0, hw, lw);
        ch[r * D2 + c2] = hw; cl[r * D2 + c2] = lw;
        splitp(oacc[nb][2] * inv1, oacc[nb][3] * inv1, hw, lw);
        ch[(r + 8) * D2 + c2] = hw; cl[(r + 8) * D2 + c2] = lw;
    }
}

// ---------------------------------------------------------------------------
extern "C" void kernel_launch(void* const* d_in, const int* in_sizes, int n_in,
                              void* d_out, int out_size)
{
    const float* x = (const float*)d_in[0];
    const float* W[4] = {(const float*)d_in[1], (const float*)d_in[2],
                         (const float*)d_in[3], (const float*)d_in[4]};

    uint32_t *xh, *xl, *qh, *ql, *kh, *kl, *vh, *vl, *ch, *cl, *wh, *wl;
    cudaGetSymbolAddress((void**)&xh, g_xh); cudaGetSymbolAddress((void**)&xl, g_xl);
    cudaGetSymbolAddress((void**)&qh, g_qh); cudaGetSymbolAddress((void**)&ql, g_ql);
    cudaGetSymbolAddress((void**)&kh, g_kh); cudaGetSymbolAddress((void**)&kl, g_kl);
    cudaGetSymbolAddress((void**)&vh, g_vh); cudaGetSymbolAddress((void**)&vl, g_vl);
    cudaGetSymbolAddress((void**)&ch, g_ch); cudaGetSymbolAddress((void**)&cl, g_cl);
    cudaGetSymbolAddress((void**)&wh, g_wh); cudaGetSymbolAddress((void**)&wl, g_wl);

    cudaFuncSetAttribute(gemm_bf, cudaFuncAttributeMaxDynamicSharedMemorySize, G_SMEM);
    cudaFuncSetAttribute(attn_tc, cudaFuncAttributeMaxDynamicSharedMemorySize, A_SMEM);

    // 1) convert inputs to bf16 hi/lo planes
    const int xn4 = MTOT * DD / 4, wn4 = DD * DD / 4;
    convert_bf<<<(xn4 + 255) / 256, 256>>>(x, xh, xl, xn4);
    for (int w = 0; w < 4; w++)
        convert_bf<<<(wn4 + 255) / 256, 256>>>(W[w], wh + (size_t)w * DD * D2,
                                               wl + (size_t)w * DD * D2, wn4);

    // 2) projections (Q scaled by 1/sqrt(DK) = 0.125 in epilogue)
    dim3 gg(DD / 128, MTOT / 128);   // (8, 64)
    gemm_bf<<<gg, 256, G_SMEM>>>(xh, xl, wh + 0 * (size_t)DD * D2, wl + 0 * (size_t)DD * D2,
                                 nullptr, qh, ql, 0.125f);
    gemm_bf<<<gg, 256, G_SMEM>>>(xh, xl, wh + 1 * (size_t)DD * D2, wl + 1 * (size_t)DD * D2,
                                 nullptr, kh, kl, 1.0f);
    gemm_bf<<<gg, 256, G_SMEM>>>(xh, xl, wh + 2 * (size_t)DD * D2, wl + 2 * (size_t)DD * D2,
                                 nullptr, vh, vl, 1.0f);

    // 3) attention (planes in, planes out)
    attn_tc<<<dim3(SS / 128, HH, BB), 256, A_SMEM>>>(qh, ql, kh, kl, vh, vl, ch, cl);

    // 4) output projection -> fp32 d_out
    gemm_bf<<<gg, 256, G_SMEM>>>(ch, cl, wh + 3 * (size_t)DD * D2, wl + 3 * (size_t)DD * D2,
                                 (float*)d_out, nullptr, nullptr, 1.0f);
}

// round 14
// speedup vs baseline: 1.2356x; 1.0810x over previous
#include <cuda_runtime.h>
#include <cuda_bf16.h>
#include <cstdint>

#define BB   4
#define SS   2048
#define DD   1024
#define HH   16
#define DK   64
#define MTOT (BB * SS)
#define D2   (DD / 2)   // u32 (bf16x2) per row

// Q scale 1/sqrt(64) * log2(e)  (softmax runs in exp2 domain)
#define QSCALE 0.18033688011112042f

// bf16x2 hi/lo planes in global scratch (no runtime allocation allowed)
__device__ uint32_t g_xh[(size_t)MTOT * D2], g_xl[(size_t)MTOT * D2];
__device__ uint32_t g_qh[(size_t)MTOT * D2], g_ql[(size_t)MTOT * D2];
__device__ uint32_t g_kh[(size_t)MTOT * D2], g_kl[(size_t)MTOT * D2];
__device__ uint32_t g_vh[(size_t)MTOT * D2], g_vl[(size_t)MTOT * D2];
__device__ uint32_t g_ch[(size_t)MTOT * D2], g_cl[(size_t)MTOT * D2];
__device__ uint32_t g_wh[4][(size_t)DD * D2], g_wl[4][(size_t)DD * D2];

// ---------------------------------------------------------------------------
__device__ __forceinline__ void mma16(float* d,
                                      uint32_t a0, uint32_t a1, uint32_t a2, uint32_t a3,
                                      uint32_t b0, uint32_t b1) {
    asm volatile(
        "mma.sync.aligned.m16n8k16.row.col.f32.bf16.bf16.f32 "
        "{%0,%1,%2,%3},{%4,%5,%6,%7},{%8,%9},{%0,%1,%2,%3};"
        : "+f"(d[0]), "+f"(d[1]), "+f"(d[2]), "+f"(d[3])
        : "r"(a0), "r"(a1), "r"(a2), "r"(a3), "r"(b0), "r"(b1));
}

__device__ __forceinline__ void splitp(float x0, float x1, uint32_t& hi, uint32_t& lo) {
    __nv_bfloat162 h = __floats2bfloat162_rn(x0, x1);
    float f0 = __bfloat162float(h.x), f1 = __bfloat162float(h.y);
    __nv_bfloat162 l = __floats2bfloat162_rn(x0 - f0, x1 - f1);
    hi = *reinterpret_cast<uint32_t*>(&h);
    lo = *reinterpret_cast<uint32_t*>(&l);
}

__device__ __forceinline__ uint32_t smem_u32(const void* p) {
    uint32_t a;
    asm("{ .reg .u64 t; cvta.to.shared.u64 t, %1; cvt.u32.u64 %0, t; }"
        : "=r"(a) : "l"(p));
    return a;
}

__device__ __forceinline__ void ldmx4(uint32_t& r0, uint32_t& r1,
                                      uint32_t& r2, uint32_t& r3, uint32_t addr) {
    asm volatile("ldmatrix.sync.aligned.m8n8.x4.shared.b16 {%0,%1,%2,%3}, [%4];"
                 : "=r"(r0), "=r"(r1), "=r"(r2), "=r"(r3) : "r"(addr));
}

__device__ __forceinline__ void ldmx4t(uint32_t& r0, uint32_t& r1,
                                       uint32_t& r2, uint32_t& r3, uint32_t addr) {
    asm volatile("ldmatrix.sync.aligned.m8n8.x4.trans.shared.b16 {%0,%1,%2,%3}, [%4];"
                 : "=r"(r0), "=r"(r1), "=r"(r2), "=r"(r3) : "r"(addr));
}

__device__ __forceinline__ float ex2f(float x) {
    float r;
    asm("ex2.approx.f32 %0, %1;" : "=f"(r) : "f"(x));
    return r;
}

#define CP16(dst_u32, src) \
    asm volatile("cp.async.cg.shared.global [%0], [%1], 16;" \
                 :: "r"(sb + 4u * (uint32_t)(dst_u32)), "l"((const void*)(src)))
#define CP_COMMIT() asm volatile("cp.async.commit_group;")
#define CP_WAIT(n)  asm volatile("cp.async.wait_group %0;" :: "n"(n))

// ===========================================================================
// One-shot conversion of x + all 4 weights to bf16 hi/lo planes
// ===========================================================================
#define XN4 (MTOT * DD / 4)   // 2097152 float4 chunks
#define WN4 (DD * DD / 4)     // 262144

__global__ __launch_bounds__(256) void convert_all(
    const float* __restrict__ x,
    const float* __restrict__ w0, const float* __restrict__ w1,
    const float* __restrict__ w2, const float* __restrict__ w3,
    uint32_t* __restrict__ xh, uint32_t* __restrict__ xl,
    uint32_t* __restrict__ whb, uint32_t* __restrict__ wlb)
{
    int id = blockIdx.x * 256 + threadIdx.x;
    const float* src;
    uint32_t *hi, *lo;
    int r;
    if (id < XN4) {
        src = x; hi = xh; lo = xl; r = id;
    } else {
        int q = (id - XN4) >> 18;          // WN4 = 2^18
        r = (id - XN4) & (WN4 - 1);
        src = (q == 0) ? w0 : (q == 1) ? w1 : (q == 2) ? w2 : w3;
        hi = whb + (size_t)q * DD * D2;
        lo = wlb + (size_t)q * DD * D2;
    }
    float4 v = ((const float4*)src)[r];
    uint32_t h0, l0, h1, l1;
    splitp(v.x, v.y, h0, l0);
    splitp(v.z, v.w, h1, l1);
    ((uint2*)hi)[r] = make_uint2(h0, h1);
    ((uint2*)lo)[r] = make_uint2(l0, l1);
}

// ===========================================================================
// Shared GEMM mainloop: acc += A[row0:+128] * B[col0:+128]^T over K=1024.
// cp.async double buffer + ldmatrix fragments (identical math to R13).
// ===========================================================================
#define GSTR    20
#define G_AH    0
#define G_AL    2560
#define G_BH    5120
#define G_BL    7680
#define G_STAGE 10240
#define G_SMEM  (2 * G_STAGE * 4)   // 81920 B

__device__ __forceinline__ void gemm_main(
    const uint32_t* __restrict__ Agh, const uint32_t* __restrict__ Agl,
    const uint32_t* __restrict__ Bgh, const uint32_t* __restrict__ Bgl,
    uint32_t sb, int tid, float acc[2][8][4])
{
    const int lane = tid & 31, wid = tid >> 5;
    const int wm = wid & 3, wn = wid >> 2;
    const int a_lr = lane & 15, a_lk = (lane >> 4) * 4;
    const int b_lc = (lane & 7) + ((lane >> 4) << 3), b_lk = ((lane >> 3) & 1) * 4;

#define G_ISSUE(kt) do {                                                       \
    uint32_t bs_ = ((kt) & 1) * G_STAGE;                                       \
    _Pragma("unroll")                                                          \
    for (int i = 0; i < 2; i++) {                                              \
        int idx = tid + i * 256, r = idx >> 2, cu = (idx & 3) * 4;             \
        size_t go = (size_t)r * D2 + (kt) * 16 + cu;                           \
        uint32_t so = r * GSTR + cu;                                           \
        CP16(bs_ + G_AH + so, Agh + go);                                       \
        CP16(bs_ + G_AL + so, Agl + go);                                       \
        CP16(bs_ + G_BH + so, Bgh + go);                                       \
        CP16(bs_ + G_BL + so, Bgl + go);                                       \
    } } while (0)

    G_ISSUE(0); CP_COMMIT();
    G_ISSUE(1); CP_COMMIT();

    for (int kt = 0; kt < 32; kt++) {
        if (kt == 31) { CP_WAIT(0); } else { CP_WAIT(1); }
        __syncthreads();

        const uint32_t bs = (kt & 1) * G_STAGE;
#pragma unroll
        for (int ks = 0; ks < 2; ks++) {
            const int ko = ks * 8;
            uint32_t ah[2][4], al[2][4];
#pragma unroll
            for (int mb = 0; mb < 2; mb++) {
                uint32_t ao = bs + G_AH + (wm * 32 + mb * 16 + a_lr) * GSTR + ko + a_lk;
                ldmx4(ah[mb][0], ah[mb][1], ah[mb][2], ah[mb][3], sb + 4 * ao);
                ldmx4(al[mb][0], al[mb][1], al[mb][2], al[mb][3], sb + 4 * (ao + 2560));
            }
#pragma unroll
            for (int nbp = 0; nbp < 4; nbp++) {
                uint32_t bo = bs + G_BH + (wn * 64 + nbp * 16 + b_lc) * GSTR + ko + b_lk;
                uint32_t bh0, bh1, bh2, bh3, bl0, bl1, bl2, bl3;
                ldmx4(bh0, bh1, bh2, bh3, sb + 4 * bo);
                ldmx4(bl0, bl1, bl2, bl3, sb + 4 * (bo + 2560));
#pragma unroll
                for (int mb = 0; mb < 2; mb++) {
                    float* d0 = acc[mb][2 * nbp];
                    float* d1 = acc[mb][2 * nbp + 1];
                    mma16(d0, ah[mb][0], ah[mb][1], ah[mb][2], ah[mb][3], bh0, bh1);
                    mma16(d0, ah[mb][0], ah[mb][1], ah[mb][2], ah[mb][3], bl0, bl1);
                    mma16(d0, al[mb][0], al[mb][1], al[mb][2], al[mb][3], bh0, bh1);
                    mma16(d1, ah[mb][0], ah[mb][1], ah[mb][2], ah[mb][3], bh2, bh3);
                    mma16(d1, ah[mb][0], ah[mb][1], ah[mb][2], ah[mb][3], bl2, bl3);
                    mma16(d1, al[mb][0], al[mb][1], al[mb][2], al[mb][3], bh2, bh3);
                }
            }
        }
        __syncthreads();
        if (kt + 2 < 32) { G_ISSUE(kt + 2); CP_COMMIT(); }
    }
#undef G_ISSUE
}

// Fused Q/K/V projections: grid (24, 64); blockIdx.x>>3 selects weight/output.
__global__ __launch_bounds__(256, 2) void gemm_qkv(
    const uint32_t* __restrict__ Ah, const uint32_t* __restrict__ Al,
    const uint32_t* __restrict__ Whb, const uint32_t* __restrict__ Wlb,
    uint32_t* __restrict__ qh, uint32_t* __restrict__ ql,
    uint32_t* __restrict__ kh, uint32_t* __restrict__ kl,
    uint32_t* __restrict__ vh, uint32_t* __restrict__ vl)
{
    extern __shared__ uint32_t sm[];
    const uint32_t sb = smem_u32(sm);
    const int tid = threadIdx.x, lane = tid & 31, wid = tid >> 5;
    const int g = lane >> 2, t = lane & 3;
    const int wm = wid & 3, wn = wid >> 2;
    const int w = blockIdx.x >> 3;
    const int row0 = blockIdx.y * 128, col0 = (blockIdx.x & 7) * 128;

    float acc[2][8][4];
#pragma unroll
    for (int mb = 0; mb < 2; mb++)
#pragma unroll
        for (int nb = 0; nb < 8; nb++)
#pragma unroll
            for (int i = 0; i < 4; i++) acc[mb][nb][i] = 0.0f;

    gemm_main(Ah + (size_t)row0 * D2, Al + (size_t)row0 * D2,
              Whb + (size_t)w * DD * D2 + (size_t)col0 * D2,
              Wlb + (size_t)w * DD * D2 + (size_t)col0 * D2,
              sb, tid, acc);

    uint32_t* Ch = (w == 0) ? qh : (w == 1) ? kh : vh;
    uint32_t* Cl = (w == 0) ? ql : (w == 1) ? kl : vl;
    const float scale = (w == 0) ? QSCALE : 1.0f;

#pragma unroll
    for (int mb = 0; mb < 2; mb++) {
        int r = row0 + wm * 32 + mb * 16 + g;
#pragma unroll
        for (int nb = 0; nb < 8; nb++) {
            int c2 = col0 / 2 + wn * 32 + nb * 4 + t;
            uint32_t hw, lw;
            splitp(acc[mb][nb][0] * scale, acc[mb][nb][1] * scale, hw, lw);
            Ch[(size_t)r * D2 + c2] = hw; Cl[(size_t)r * D2 + c2] = lw;
            splitp(acc[mb][nb][2] * scale, acc[mb][nb][3] * scale, hw, lw);
            Ch[(size_t)(r + 8) * D2 + c2] = hw; Cl[(size_t)(r + 8) * D2 + c2] = lw;
        }
    }
}

// O projection: fp32 output.
__global__ __launch_bounds__(256, 2) void gemm_o(
    const uint32_t* __restrict__ Ah, const uint32_t* __restrict__ Al,
    const uint32_t* __restrict__ Bh, const uint32_t* __restrict__ Bl,
    float* __restrict__ Cf)
{
    extern __shared__ uint32_t sm[];
    const uint32_t sb = smem_u32(sm);
    const int tid = threadIdx.x, lane = tid & 31, wid = tid >> 5;
    const int g = lane >> 2, t = lane & 3;
    const int wm = wid & 3, wn = wid >> 2;
    const int row0 = blockIdx.y * 128, col0 = blockIdx.x * 128;

    float acc[2][8][4];
#pragma unroll
    for (int mb = 0; mb < 2; mb++)
#pragma unroll
        for (int nb = 0; nb < 8; nb++)
#pragma unroll
            for (int i = 0; i < 4; i++) acc[mb][nb][i] = 0.0f;

    gemm_main(Ah + (size_t)row0 * D2, Al + (size_t)row0 * D2,
              Bh + (size_t)col0 * D2, Bl + (size_t)col0 * D2, sb, tid, acc);

#pragma unroll
    for (int mb = 0; mb < 2; mb++) {
        int r = row0 + wm * 32 + mb * 16 + g;
#pragma unroll
        for (int nb = 0; nb < 8; nb++) {
            int c = col0 + wn * 64 + nb * 8 + 2 * t;
            *(float2*)(Cf + (size_t)r * DD + c)       = make_float2(acc[mb][nb][0], acc[mb][nb][1]);
            *(float2*)(Cf + (size_t)(r + 8) * DD + c) = make_float2(acc[mb][nb][2], acc[mb][nb][3]);
        }
    }
}

// ===========================================================================
// Flash attention: 128q x 32k tiles, 256 threads, 3-stage cp.async ring,
// single barrier per tile, ldmatrix for Q/K/V fragments, exp2 softmax.
// smem: QH 0, QL 4608; stage s (0..2) at 9216+s*4608: KH,KL,VH,VL (1152 each)
// ===========================================================================
#define AQH  0
#define AQL  4608
#define AST  9216
#define ASTG 4608
#define A_SMEM (23040 * 4)   // 92160 B  (2 CTAs/SM: 2x92160 < 227KB)
#define QSTR 36
#define KSTR 36
#define VSTR 36

__global__ __launch_bounds__(256, 2) void attn_tc(
    const uint32_t* __restrict__ qh, const uint32_t* __restrict__ ql,
    const uint32_t* __restrict__ kh, const uint32_t* __restrict__ kl,
    const uint32_t* __restrict__ vh, const uint32_t* __restrict__ vl,
    uint32_t* __restrict__ ch, uint32_t* __restrict__ cl)
{
    extern __shared__ uint32_t sm[];
    const uint32_t sb = smem_u32(sm);
    const int tid = threadIdx.x, lane = tid & 31, wid = tid >> 5;
    const int g = lane >> 2, t = lane & 3;
    const int b = blockIdx.z, h = blockIdx.y, q0 = blockIdx.x * 128;

    const size_t qrow0 = (size_t)(b * SS) + q0;
    const size_t krow0 = (size_t)(b * SS);
    const int hcol = h * (DK / 2);

    // ldmatrix lane addressing (same as GEMM)
    const int a_lr = lane & 15, a_lk = (lane >> 4) * 4;
    const int b_lc = (lane & 7) + ((lane >> 4) << 3), b_lk = ((lane >> 3) & 1) * 4;
    const int lrow = lane & 7, q4 = lane >> 3;
    const int lm_row = (q4 & 1) * 8 + lrow;
    const int lm_dk  = (q4 >> 1) * 8;

    // Q planes: plain vector loads (one-shot)
#pragma unroll
    for (int i = 0; i < 4; i++) {
        int idx = tid + i * 256, r = idx >> 3, cu = (idx & 7) * 4;
        size_t go = (qrow0 + r) * D2 + hcol + cu;
        *(uint4*)(sm + AQH + r * QSTR + cu) = *(const uint4*)(qh + go);
        *(uint4*)(sm + AQL + r * QSTR + cu) = *(const uint4*)(ql + go);
    }

    // K/V stage fill: 4 planes x 32 rows x 32 u32 = 1024 chunks -> 4/thread
#define A_ISSUE(kt) do {                                                       \
    uint32_t stg_ = AST + ((kt) % 3) * ASTG;                                   \
    _Pragma("unroll")                                                          \
    for (int i = 0; i < 4; i++) {                                              \
        int idx = tid + i * 256;                                               \
        int pl = idx >> 8, j = idx & 255, r = j >> 3, cu = (j & 7) * 4;        \
        const uint32_t* sp = (pl == 0) ? kh : (pl == 1) ? kl                   \
                             : (pl == 2) ? vh : vl;                            \
        size_t go = (krow0 + (kt) * 32 + r) * D2 + hcol + cu;                  \
        CP16(stg_ + pl * 1152 + r * 36 + cu, sp + go);                         \
    } } while (0)

    float m0 = -1e30f, m1 = -1e30f, l0s = 0.0f, l1s = 0.0f;
    float oacc[8][4];
#pragma unroll
    for (int nb = 0; nb < 8; nb++)
#pragma unroll
        for (int i = 0; i < 4; i++) oacc[nb][i] = 0.0f;

    A_ISSUE(0); CP_COMMIT();
    A_ISSUE(1); CP_COMMIT();

    for (int kt = 0; kt < SS / 32; kt++) {
        if (kt == SS / 32 - 1) { CP_WAIT(0); } else { CP_WAIT(1); }
        __syncthreads();   // single barrier per tile (3-stage ring)
        if (kt + 2 < SS / 32) { A_ISSUE(kt + 2); CP_COMMIT(); }

        const uint32_t stg = AST + (kt % 3) * ASTG;
        const uint32_t AKH_ = stg, AKL_ = stg + 1152;
        const uint32_t AVH_ = stg + 2304, AVL_ = stg + 3456;

        // S[16 x 32] = Q * K^T per warp (ldmatrix fragments)
        float sacc[4][4];
#pragma unroll
        for (int nb = 0; nb < 4; nb++)
#pragma unroll
            for (int i = 0; i < 4; i++) sacc[nb][i] = 0.0f;
#pragma unroll
        for (int ks = 0; ks < 4; ks++) {
            const int ko = ks * 8;
            uint32_t aro = (wid * 16 + a_lr) * QSTR + ko + a_lk;
            uint32_t ah0, ah1, ah2, ah3, al0, al1, al2, al3;
            ldmx4(ah0, ah1, ah2, ah3, sb + 4 * (AQH + aro));
            ldmx4(al0, al1, al2, al3, sb + 4 * (AQL + aro));
#pragma unroll
            for (int nbp = 0; nbp < 2; nbp++) {
                uint32_t bro = (nbp * 16 + b_lc) * KSTR + ko + b_lk;
                uint32_t bh0, bh1, bh2, bh3, bl0, bl1, bl2, bl3;
                ldmx4(bh0, bh1, bh2, bh3, sb + 4 * (AKH_ + bro));
                ldmx4(bl0, bl1, bl2, bl3, sb + 4 * (AKL_ + bro));
                float* s0 = sacc[2 * nbp];
                float* s1 = sacc[2 * nbp + 1];
                mma16(s0, ah0, ah1, ah2, ah3, bh0, bh1);
                mma16(s0, ah0, ah1, ah2, ah3, bl0, bl1);
                mma16(s0, al0, al1, al2, al3, bh0, bh1);
                mma16(s1, ah0, ah1, ah2, ah3, bh2, bh3);
                mma16(s1, ah0, ah1, ah2, ah3, bl2, bl3);
                mma16(s1, al0, al1, al2, al3, bh2, bh3);
            }
        }

        // online softmax in exp2 domain (warp-private rows)
        float rm0 = -1e30f, rm1 = -1e30f;
#pragma unroll
        for (int nb = 0; nb < 4; nb++) {
            rm0 = fmaxf(rm0, fmaxf(sacc[nb][0], sacc[nb][1]));
            rm1 = fmaxf(rm1, fmaxf(sacc[nb][2], sacc[nb][3]));
        }
        rm0 = fmaxf(rm0, __shfl_xor_sync(0xffffffffu, rm0, 1));
        rm0 = fmaxf(rm0, __shfl_xor_sync(0xffffffffu, rm0, 2));
        rm1 = fmaxf(rm1, __shfl_xor_sync(0xffffffffu, rm1, 1));
        rm1 = fmaxf(rm1, __shfl_xor_sync(0xffffffffu, rm1, 2));
        float mn0 = fmaxf(m0, rm0), mn1 = fmaxf(m1, rm1);
        float a0 = ex2f(m0 - mn0), a1 = ex2f(m1 - mn1);
        m0 = mn0; m1 = mn1;

        float ls0 = 0.0f, ls1 = 0.0f;
        uint32_t pfh[2][4], pfl[2][4];
#pragma unroll
        for (int nb = 0; nb < 4; nb++) {
            float p0 = ex2f(sacc[nb][0] - mn0), p1 = ex2f(sacc[nb][1] - mn0);
            float p2 = ex2f(sacc[nb][2] - mn1), p3 = ex2f(sacc[nb][3] - mn1);
            ls0 += p0 + p1; ls1 += p2 + p3;
            const int ks = nb >> 1, half = nb & 1;
            splitp(p0, p1, pfh[ks][2 * half],     pfl[ks][2 * half]);
            splitp(p2, p3, pfh[ks][2 * half + 1], pfl[ks][2 * half + 1]);
        }
        ls0 += __shfl_xor_sync(0xffffffffu, ls0, 1);
        ls0 += __shfl_xor_sync(0xffffffffu, ls0, 2);
        ls1 += __shfl_xor_sync(0xffffffffu, ls1, 1);
        ls1 += __shfl_xor_sync(0xffffffffu, ls1, 2);
        l0s = l0s * a0 + ls0; l1s = l1s * a1 + ls1;
#pragma unroll
        for (int nb = 0; nb < 8; nb++) {
            oacc[nb][0] *= a0; oacc[nb][1] *= a0;
            oacc[nb][2] *= a1; oacc[nb][3] *= a1;
        }

        // O += P * V (V B-frags via ldmatrix.x4.trans)
#pragma unroll
        for (int ks = 0; ks < 2; ks++) {
#pragma unroll
            for (int nbp = 0; nbp < 4; nbp++) {
                const int dk0 = nbp * 16;
                uint32_t off = (uint32_t)((ks * 16 + lm_row) * VSTR + (dk0 + lm_dk) / 2);
                uint32_t vh0, vh1, vh2, vh3, vl0, vl1, vl2, vl3;
                ldmx4t(vh0, vh1, vh2, vh3, sb + 4 * (AVH_ + off));
                ldmx4t(vl0, vl1, vl2, vl3, sb + 4 * (AVL_ + off));
                float* d0 = oacc[2 * nbp];
                float* d1 = oacc[2 * nbp + 1];
                mma16(d0, pfh[ks][0], pfh[ks][1], pfh[ks][2], pfh[ks][3], vh0, vh1);
                mma16(d0, pfh[ks][0], pfh[ks][1], pfh[ks][2], pfh[ks][3], vl0, vl1);
                mma16(d0, pfl[ks][0], pfl[ks][1], pfl[ks][2], pfl[ks][3], vh0, vh1);
                mma16(d1, pfh[ks][0], pfh[ks][1], pfh[ks][2], pfh[ks][3], vh2, vh3);
                mma16(d1, pfh[ks][0], pfh[ks][1], pfh[ks][2], pfh[ks][3], vl2, vl3);
                mma16(d1, pfl[ks][0], pfl[ks][1], pfl[ks][2], pfl[ks][3], vh2, vh3);
            }
        }
    }

    // epilogue: write ctx as bf16 planes
    const float inv0 = 1.0f / l0s, inv1 = 1.0f / l1s;
#pragma unroll
    for (int nb = 0; nb < 8; nb++) {
        size_t r = qrow0 + wid * 16 + g;
        int c2 = hcol + nb * 4 + t;
        uint32_t hw, lw;
        splitp(oacc[nb][0] * inv0, oacc[nb][1] * inv0, hw, lw);
        ch[r * D2 + c2] = hw; cl[r * D2 + c2] = lw;
        splitp(oacc[nb][2] * inv1, oacc[nb][3] * inv1, hw, lw);
        ch[(r + 8) * D2 + c2] = hw; cl[(r + 8) * D2 + c2] = lw;
    }
}

// ---------------------------------------------------------------------------
extern "C" void kernel_launch(void* const* d_in, const int* in_sizes, int n_in,
                              void* d_out, int out_size)
{
    const float* x = (const float*)d_in[0];

    uint32_t *xh, *xl, *qh, *ql, *kh, *kl, *vh, *vl, *ch, *cl, *wh, *wl;
    cudaGetSymbolAddress((void**)&xh, g_xh); cudaGetSymbolAddress((void**)&xl, g_xl);
    cudaGetSymbolAddress((void**)&qh, g_qh); cudaGetSymbolAddress((void**)&ql, g_ql);
    cudaGetSymbolAddress((void**)&kh, g_kh); cudaGetSymbolAddress((void**)&kl, g_kl);
    cudaGetSymbolAddress((void**)&vh, g_vh); cudaGetSymbolAddress((void**)&vl, g_vl);
    cudaGetSymbolAddress((void**)&ch, g_ch); cudaGetSymbolAddress((void**)&cl, g_cl);
    cudaGetSymbolAddress((void**)&wh, g_wh); cudaGetSymbolAddress((void**)&wl, g_wl);

    cudaFuncSetAttribute(gemm_qkv, cudaFuncAttributeMaxDynamicSharedMemorySize, G_SMEM);
    cudaFuncSetAttribute(gemm_o,   cudaFuncAttributeMaxDynamicSharedMemorySize, G_SMEM);
    cudaFuncSetAttribute(attn_tc,  cudaFuncAttributeMaxDynamicSharedMemorySize, A_SMEM);

    // 1) convert x + 4 weights (one launch)
    const int total4 = XN4 + 4 * WN4;
    convert_all<<<total4 / 256, 256>>>(x, (const float*)d_in[1], (const float*)d_in[2],
                                       (const float*)d_in[3], (const float*)d_in[4],
                                       xh, xl, wh, wl);

    // 2) fused Q/K/V projections (Q scaled by 0.125*log2e in epilogue)
    gemm_qkv<<<dim3(24, MTOT / 128), 256, G_SMEM>>>(xh, xl, wh, wl,
                                                    qh, ql, kh, kl, vh, vl);

    // 3) attention (planes in, planes out)
    attn_tc<<<dim3(SS / 128, HH, BB), 256, A_SMEM>>>(qh, ql, kh, kl, vh, vl, ch, cl);

    // 4) output projection -> fp32 d_out
    gemm_o<<<dim3(8, MTOT / 128), 256, G_SMEM>>>(ch, cl,
                                                 wh + 3 * (size_t)DD * D2,
                                                 wl + 3 * (size_t)DD * D2,
                                                 (float*)d_out);
}